// round 14
// baseline (speedup 1.0000x reference)
#include <cuda_runtime.h>
#include <cstdint>

#define NPTS 8192
#define KNN  8

typedef unsigned long long u64t;

__device__ __forceinline__ u64t pk2(float x) {
    u64t r; asm("mov.b64 %0, {%1, %1};" : "=l"(r) : "f"(x)); return r;
}
__device__ __forceinline__ u64t f2fma(u64t a, u64t b, u64t c) {
    u64t d; asm("fma.rn.f32x2 %0, %1, %2, %3;" : "=l"(d) : "l"(a), "l"(b), "l"(c)); return d;
}
__device__ __forceinline__ float2 up2(u64t v) {
    float2 f; asm("mov.b64 {%0, %1}, %2;" : "=f"(f.x), "=f"(f.y) : "l"(v)); return f;
}

// ---------------- scratch ----------------
__device__ __align__(16) float4 g_pts4[NPTS];
__device__ int                  g_idx[NPTS * KNN];
__device__ __align__(16) float  g_qp1[NPTS * 128];
__device__ __align__(16) float  g_x1 [NPTS * 128];
__device__ __align__(16) float  g_qp2[NPTS * 256];
__device__ __align__(16) float  g_wcat[128 * 256];

// ---------------- prep ----------------
__global__ void k_prep(const float* __restrict__ pc) {
    int i = blockIdx.x * blockDim.x + threadIdx.x;
    if (i < NPTS) {
        float x = pc[3*i], y = pc[3*i+1], z = pc[3*i+2];
        float s = fmaf(x, x, fmaf(y, y, z*z));
        g_pts4[i] = make_float4(x, y, z, s);
    }
}

// ---------------- KNN (R5/R11 shape) ----------------
__global__ void k_knn() {
    extern __shared__ char sm[];
    float4* sp = (float4*)sm;
    float*  md = (float*)(sm + NPTS * 16);
    int*    mi = (int*)  (sm + NPTS * 16 + 64 * 33 * 4);

    int tid = threadIdx.x;
    for (int t = tid; t < NPTS; t += 256) sp[t] = g_pts4[t];
    __syncthreads();

    int part = tid >> 6;
    int lp   = tid & 63;
    int pt   = blockIdx.x * 64 + lp;
    float4 me = sp[pt];

    float bd[8]; int bj[8];
#pragma unroll
    for (int s = 0; s < 8; s++) { bd[s] = 3.4e38f; bj[s] = 0x7fffffff; }

    int j0 = part * 2048;
#pragma unroll 4
    for (int jj = 0; jj < 2048; jj++) {
        int j = j0 + jj;
        float4 o = sp[j];
        float dot = fmaf(me.x, o.x, fmaf(me.y, o.y, me.z * o.z));
        float d   = fmaf(-2.0f, dot, me.w + o.w);
        if (d < bd[7]) {
            bd[7] = d; bj[7] = j;
#pragma unroll
            for (int s = 7; s > 0; s--) {
                if (bd[s] < bd[s-1]) {
                    float td = bd[s]; bd[s] = bd[s-1]; bd[s-1] = td;
                    int   tj = bj[s]; bj[s] = bj[s-1]; bj[s-1] = tj;
                }
            }
        }
    }
#pragma unroll
    for (int s = 0; s < 8; s++) {
        md[lp * 33 + part * 8 + s] = bd[s];
        mi[lp * 33 + part * 8 + s] = bj[s];
    }
    __syncthreads();

    if (tid < 64) {
        float* rd = md + tid * 33;
        int*   ri = mi + tid * 33;
        int po = (blockIdx.x * 64 + tid) * KNN;
        for (int s = 0; s < 8; s++) {
            float bdd = 3.4e38f; int bjj = 0x7fffffff; int bp = 0;
            for (int t = 0; t < 32; t++) {
                float dd = rd[t]; int jj = ri[t];
                if (dd < bdd || (dd == bdd && jj < bjj)) { bdd = dd; bjj = jj; bp = t; }
            }
            rd[bp] = 3.4e38f;
            g_idx[po + s] = bjj;
        }
    }
}

// ---------------- P1 ----------------
__global__ void k_lin1(const float* __restrict__ W1, const float* __restrict__ pc) {
    int g = blockIdx.x * blockDim.x + threadIdx.x;
    if (g >= NPTS * 32) return;
    int i = g >> 5, q = g & 31;
    float x0 = pc[3*i], x1 = pc[3*i+1], x2 = pc[3*i+2];
    bool isQ = (q < 16);
    int c = (isQ ? q : q - 16) * 4;
    float v[4];
#pragma unroll
    for (int u = 0; u < 4; u++) {
        float wa0 = W1[0*64 + c+u], wa1 = W1[1*64 + c+u], wa2 = W1[2*64 + c+u];
        float wb0 = W1[3*64 + c+u], wb1 = W1[4*64 + c+u], wb2 = W1[5*64 + c+u];
        if (isQ) v[u] = x0*(wa0-wb0) + x1*(wa1-wb1) + x2*(wa2-wb2);
        else     v[u] = x0*wb0 + x1*wb1 + x2*wb2;
    }
    *(float4*)&g_qp1[i * 128 + q * 4] = make_float4(v[0], v[1], v[2], v[3]);
}

// ---------------- Wcat ----------------
__global__ void k_wcat(const float* __restrict__ W3) {
    int g = blockIdx.x * blockDim.x + threadIdx.x;
    if (g >= 128 * 256) return;
    int m = g >> 8, n = g & 255;
    float v;
    if (n < 128) v = W3[m * 128 + n] - W3[(m + 128) * 128 + n];
    else         v = W3[(m + 128) * 128 + (n - 128)];
    g_wcat[m * 256 + n] = v;
}

// ---------------- EC1: R11 fused GEMM (64-row tiles, unchanged) ----------------
template<int KDIM, int KC, int NOUT, bool EDGE, bool RELU_OUT>
__global__ void __launch_bounds__(256) k_gemm(
    const float* __restrict__ qA, const float* __restrict__ pB, int qstride,
    const float* __restrict__ bK, const float* __restrict__ Wg,
    const float* __restrict__ bN, float* __restrict__ out)
{
    extern __shared__ float smf[];
    float* As = smf;
    float* Ws = smf + KDIM * 64;
    int tid = threadIdx.x;
    int blk = blockIdx.x;
    int nt0 = blockIdx.y * 128;

    {
        const int TASKS = 64 * (KDIM / 4);
        int base64 = blk * 64;
        for (int t = tid; t < TASKS; t += 256) {
            int rr = t & 63, c4 = t >> 6;
            float4 v;
            if (EDGE) {
                int i = (base64 + rr) >> 3;
                int j = g_idx[base64 + rr];
                float4 q = *(const float4*)&qA[i * qstride + c4 * 4];
                float4 p = *(const float4*)&pB[(long)j * qstride + c4 * 4];
                float4 b = *(const float4*)&bK[c4 * 4];
                v.x = fmaxf(q.x + p.x + b.x, 0.0f);
                v.y = fmaxf(q.y + p.y + b.y, 0.0f);
                v.z = fmaxf(q.z + p.z + b.z, 0.0f);
                v.w = fmaxf(q.w + p.w + b.w, 0.0f);
            } else {
                v = *(const float4*)&qA[(long)(base64 + rr) * qstride + c4 * 4];
            }
            As[(c4*4 + 0) * 64 + rr] = v.x;
            As[(c4*4 + 1) * 64 + rr] = v.y;
            As[(c4*4 + 2) * 64 + rr] = v.z;
            As[(c4*4 + 3) * 64 + rr] = v.w;
        }
    }

    int tm = tid >> 5, tn = tid & 31;
    u64t acc2[4][4];
#pragma unroll
    for (int p = 0; p < 4; p++)
#pragma unroll
        for (int n = 0; n < 4; n++) acc2[p][n] = 0ull;

    const float4* Wg4 = (const float4*)Wg;
    for (int kc = 0; kc < KDIM / KC; kc++) {
        __syncthreads();
        {
            float4* Ws4 = (float4*)Ws;
#pragma unroll 4
            for (int t = tid; t < KC * 32; t += 256)
                Ws4[t] = Wg4[((kc * KC + (t >> 5)) * NOUT + nt0) / 4 + (t & 31)];
        }
        __syncthreads();

        const float* Ak = As + kc * KC * 64;
#pragma unroll 4
        for (int c = 0; c < KC; c++) {
            ulonglong2 av0 = *(const ulonglong2*)&Ak[c * 64 + tm * 8];
            ulonglong2 av1 = *(const ulonglong2*)&Ak[c * 64 + tm * 8 + 4];
            u64t ap[4] = {av0.x, av0.y, av1.x, av1.y};
            float4 w = *(const float4*)&Ws[c * 128 + tn * 4];
            u64t wd[4] = {pk2(w.x), pk2(w.y), pk2(w.z), pk2(w.w)};
#pragma unroll
            for (int p = 0; p < 4; p++)
#pragma unroll
                for (int n = 0; n < 4; n++)
                    acc2[p][n] = f2fma(ap[p], wd[n], acc2[p][n]);
        }
    }

    if (EDGE) {
        int pt = blk * 8 + tm;
        float res[4];
#pragma unroll
        for (int n = 0; n < 4; n++) {
            float2 v0 = up2(acc2[0][n]);
            float2 v1 = up2(acc2[1][n]);
            float2 v2 = up2(acc2[2][n]);
            float2 v3 = up2(acc2[3][n]);
            float m = fmaxf(fmaxf(fmaxf(v0.x, v0.y), fmaxf(v1.x, v1.y)),
                            fmaxf(fmaxf(v2.x, v2.y), fmaxf(v3.x, v3.y)));
            m += bN[nt0 + tn * 4 + n];
            if (RELU_OUT) m = fmaxf(m, 0.0f);
            res[n] = m;
        }
        *(float4*)&out[(long)pt * NOUT + nt0 + tn * 4] =
            make_float4(res[0], res[1], res[2], res[3]);
    } else {
        int base = blk * 64;
#pragma unroll
        for (int p = 0; p < 4; p++) {
            float2 c0 = up2(acc2[p][0]);
            float2 c1 = up2(acc2[p][1]);
            float2 c2 = up2(acc2[p][2]);
            float2 c3 = up2(acc2[p][3]);
            int row0 = base + tm * 8 + 2 * p;
            *(float4*)&out[(long)row0 * NOUT + nt0 + tn * 4] =
                make_float4(c0.x, c1.x, c2.x, c3.x);
            *(float4*)&out[(long)(row0 + 1) * NOUT + nt0 + tn * 4] =
                make_float4(c0.y, c1.y, c2.y, c3.y);
        }
    }
}

// ---------------- EC2/P2: 128-row-tile GEMM, warp=16 rows, thread=16x4 ----------------
// Block: 128 rows x 128 cols, 256 threads. Warp tm covers rows [tm*16, tm*16+16)
// (A = 4x 16B broadcast loads/c); lane covers 4 cols (W = 1x float4/c).
// acc2[8][4] = 32 u64. LSU/fma demand ratio ~0.5 (vs ~0.75 in 64-row shape);
// gather/sync phases and W reload traffic per output row halved.
template<int KDIM, int KC, int NOUT, bool EDGE, bool RELU_OUT>
__global__ void __launch_bounds__(256) k_gemm2(
    const float* __restrict__ qA, const float* __restrict__ pB, int qstride,
    const float* __restrict__ bK, const float* __restrict__ Wg,
    const float* __restrict__ bN, float* __restrict__ out)
{
    extern __shared__ float smf[];
    float* As = smf;                  // [KDIM][128]
    float* Ws = smf + KDIM * 128;     // [KC][128]
    int tid = threadIdx.x;
    int blk = blockIdx.x;
    int nt0 = blockIdx.y * 128;

    // generate A tile (transposed: As[c][rr]) — 128 rows, full K
    {
        const int TASKS = 128 * (KDIM / 4);
        int base128 = blk * 128;
        for (int t = tid; t < TASKS; t += 256) {
            int rr = t & 127, c4 = t >> 7;
            float4 v;
            if (EDGE) {
                int i = (base128 + rr) >> 3;
                int j = g_idx[base128 + rr];
                float4 q = *(const float4*)&qA[i * qstride + c4 * 4];
                float4 p = *(const float4*)&pB[(long)j * qstride + c4 * 4];
                float4 b = *(const float4*)&bK[c4 * 4];
                v.x = fmaxf(q.x + p.x + b.x, 0.0f);
                v.y = fmaxf(q.y + p.y + b.y, 0.0f);
                v.z = fmaxf(q.z + p.z + b.z, 0.0f);
                v.w = fmaxf(q.w + p.w + b.w, 0.0f);
            } else {
                v = *(const float4*)&qA[(long)(base128 + rr) * qstride + c4 * 4];
            }
            As[(c4*4 + 0) * 128 + rr] = v.x;
            As[(c4*4 + 1) * 128 + rr] = v.y;
            As[(c4*4 + 2) * 128 + rr] = v.z;
            As[(c4*4 + 3) * 128 + rr] = v.w;
        }
    }

    int tm = tid >> 5;        // warp -> rows [tm*16, tm*16+16)
    int tn = tid & 31;        // lane -> cols [tn*4, tn*4+4)

    u64t acc2[8][4];          // [row-pair p][col n]: rows (tm*16+2p, +2p+1)
#pragma unroll
    for (int p = 0; p < 8; p++)
#pragma unroll
        for (int n = 0; n < 4; n++) acc2[p][n] = 0ull;

    const float4* Wg4 = (const float4*)Wg;
    for (int kc = 0; kc < KDIM / KC; kc++) {
        __syncthreads();
        {
            float4* Ws4 = (float4*)Ws;
#pragma unroll 4
            for (int t = tid; t < KC * 32; t += 256)
                Ws4[t] = Wg4[((kc * KC + (t >> 5)) * NOUT + nt0) / 4 + (t & 31)];
        }
        __syncthreads();

        const float* Ak = As + kc * KC * 128;
#pragma unroll 2
        for (int c = 0; c < KC; c++) {
            const float* ar = &Ak[c * 128 + tm * 16];
            ulonglong2 av0 = *(const ulonglong2*)(ar);       // rows 0-3 (pairs 0,1)
            ulonglong2 av1 = *(const ulonglong2*)(ar + 4);   // rows 4-7
            ulonglong2 av2 = *(const ulonglong2*)(ar + 8);   // rows 8-11
            ulonglong2 av3 = *(const ulonglong2*)(ar + 12);  // rows 12-15
            u64t ap[8] = {av0.x, av0.y, av1.x, av1.y, av2.x, av2.y, av3.x, av3.y};
            float4 w = *(const float4*)&Ws[c * 128 + tn * 4];
            u64t wd[4] = {pk2(w.x), pk2(w.y), pk2(w.z), pk2(w.w)};
#pragma unroll
            for (int p = 0; p < 8; p++)
#pragma unroll
                for (int n = 0; n < 4; n++)
                    acc2[p][n] = f2fma(ap[p], wd[n], acc2[p][n]);
        }
    }

    if (EDGE) {
        // warp's 16 rows = 2 points (8 edge-rows each), register-local max
#pragma unroll
        for (int h = 0; h < 2; h++) {
            int pt = blk * 16 + tm * 2 + h;
            float res[4];
#pragma unroll
            for (int n = 0; n < 4; n++) {
                float2 m = up2(acc2[h*4][n]);
#pragma unroll
                for (int p = h*4 + 1; p < h*4 + 4; p++) {
                    float2 v = up2(acc2[p][n]);
                    m.x = fmaxf(m.x, v.x);
                    m.y = fmaxf(m.y, v.y);
                }
                float mm = fmaxf(m.x, m.y);
                mm += bN[nt0 + tn * 4 + n];
                if (RELU_OUT) mm = fmaxf(mm, 0.0f);
                res[n] = mm;
            }
            *(float4*)&out[(long)pt * NOUT + nt0 + tn * 4] =
                make_float4(res[0], res[1], res[2], res[3]);
        }
    } else {
        int base = blk * 128;
#pragma unroll
        for (int p = 0; p < 8; p++) {
            int row0 = base + tm * 16 + 2 * p;
            float2 c0 = up2(acc2[p][0]);
            float2 c1 = up2(acc2[p][1]);
            float2 c2 = up2(acc2[p][2]);
            float2 c3 = up2(acc2[p][3]);
            *(float4*)&out[(long)row0 * NOUT + nt0 + tn * 4] =
                make_float4(c0.x, c1.x, c2.x, c3.x);
            *(float4*)&out[(long)(row0 + 1) * NOUT + nt0 + tn * 4] =
                make_float4(c0.y, c1.y, c2.y, c3.y);
        }
    }
}

// ---------------- launch ----------------
extern "C" void kernel_launch(void* const* d_in, const int* in_sizes, int n_in,
                              void* d_out, int out_size) {
    const float* pc = (const float*)d_in[0];
    const float* W1 = (const float*)d_in[1];
    const float* b1 = (const float*)d_in[2];
    const float* W2 = (const float*)d_in[3];
    const float* b2 = (const float*)d_in[4];
    const float* W3 = (const float*)d_in[5];
    const float* b3 = (const float*)d_in[6];
    const float* W4 = (const float*)d_in[7];
    const float* b4 = (const float*)d_in[8];
    float* out = (float*)d_out;

    float *qp1 = nullptr, *x1 = nullptr, *qp2 = nullptr, *wcat = nullptr;
    cudaGetSymbolAddress((void**)&qp1,  g_qp1);
    cudaGetSymbolAddress((void**)&x1,   g_x1);
    cudaGetSymbolAddress((void**)&qp2,  g_qp2);
    cudaGetSymbolAddress((void**)&wcat, g_wcat);

    const int SM_KNN = NPTS * 16 + 2 * 64 * 33 * 4;
    const int SM_EC1 = (64 * 64 + 64 * 128) * 4;                    // 48KB
    const int SM_BIG = (128 * 128 + 64 * 128) * 4;                  // 96KB

    cudaFuncSetAttribute(k_knn, cudaFuncAttributeMaxDynamicSharedMemorySize, SM_KNN);
    cudaFuncSetAttribute((const void*)k_gemm<64,64,128,true,true>,
                         cudaFuncAttributeMaxDynamicSharedMemorySize, SM_EC1);
    cudaFuncSetAttribute((const void*)k_gemm2<128,64,256,false,false>,
                         cudaFuncAttributeMaxDynamicSharedMemorySize, SM_BIG);
    cudaFuncSetAttribute((const void*)k_gemm2<128,64,256,true,false>,
                         cudaFuncAttributeMaxDynamicSharedMemorySize, SM_BIG);

    // Launch order rearranged (dependency-safe) so the ncu capture slot
    // (overall launch #6 = our #4) lands on k_knn this round.
    // 1. per-point linear factors (needs W1, pc only)
    k_lin1<<<(NPTS * 32 + 255) / 256, 256>>>(W1, pc);
    // 2. Wcat (needs W3 only)
    k_wcat<<<(128 * 256 + 255) / 256, 256>>>(W3);
    // 3. pack points
    k_prep<<<(NPTS + 255) / 256, 256>>>(pc);
    // 4. knn  <-- profiled slot
    k_knn<<<NPTS / 64, 256, SM_KNN>>>();
    // 5. EdgeConv1 (R11 shape, unchanged)
    k_gemm<64,64,128,true,true><<<dim3(NPTS * KNN / 64, 1), 256, SM_EC1>>>(
        qp1, qp1 + 64, 128, b1, W2, b2, x1);
    // 6. P2: x1 @ Wcat -> qA2|pB2  (128-row tiles)
    k_gemm2<128,64,256,false,false><<<dim3(NPTS / 128, 2), 256, SM_BIG>>>(
        x1, nullptr, 128, nullptr, wcat, nullptr, qp2);
    // 7. EdgeConv2 (128-row tiles)
    k_gemm2<128,64,256,true,false><<<dim3(NPTS * KNN / 128, 2), 256, SM_BIG>>>(
        qp2, qp2 + 128, 256, b3, W4, b4, out);
}

// round 15
// speedup vs baseline: 1.5665x; 1.5665x over previous
#include <cuda_runtime.h>
#include <cstdint>

#define NPTS 8192
#define KNN  8

typedef unsigned long long u64t;

__device__ __forceinline__ u64t pk2(float x) {
    u64t r; asm("mov.b64 %0, {%1, %1};" : "=l"(r) : "f"(x)); return r;
}
__device__ __forceinline__ u64t f2fma(u64t a, u64t b, u64t c) {
    u64t d; asm("fma.rn.f32x2 %0, %1, %2, %3;" : "=l"(d) : "l"(a), "l"(b), "l"(c)); return d;
}
__device__ __forceinline__ float2 up2(u64t v) {
    float2 f; asm("mov.b64 {%0, %1}, %2;" : "=f"(f.x), "=f"(f.y) : "l"(v)); return f;
}

// ---------------- scratch ----------------
__device__ __align__(16) float4 g_pts4[NPTS];
__device__ int                  g_idx[NPTS * KNN];
__device__ __align__(16) float  g_pd[2 * NPTS * KNN];   // per-half partial top-8 dists
__device__ int                  g_pj[2 * NPTS * KNN];   // per-half partial top-8 idx
__device__ __align__(16) float  g_qp1[NPTS * 128];
__device__ __align__(16) float  g_x1 [NPTS * 128];
__device__ __align__(16) float  g_qp2[NPTS * 256];
__device__ __align__(16) float  g_wcat[128 * 256];

// ---------------- prep ----------------
__global__ void k_prep(const float* __restrict__ pc) {
    int i = blockIdx.x * blockDim.x + threadIdx.x;
    if (i < NPTS) {
        float x = pc[3*i], y = pc[3*i+1], z = pc[3*i+2];
        float s = fmaf(x, x, fmaf(y, y, z*z));
        g_pts4[i] = make_float4(x, y, z, s);
    }
}

// branchless sorted insert (caller guarantees d < bd[7]); strict < keeps lower j on ties
__device__ __forceinline__ void ins8(float (&bd)[8], int (&bj)[8], float d, int j) {
    bool p0 = d < bd[0], p1 = d < bd[1], p2 = d < bd[2], p3 = d < bd[3];
    bool p4 = d < bd[4], p5 = d < bd[5], p6 = d < bd[6];
    bd[7] = p6 ? bd[6] : d;              bj[7] = p6 ? bj[6] : j;
    bd[6] = p5 ? bd[5] : (p6 ? d : bd[6]); bj[6] = p5 ? bj[5] : (p6 ? j : bj[6]);
    bd[5] = p4 ? bd[4] : (p5 ? d : bd[5]); bj[5] = p4 ? bj[4] : (p5 ? j : bj[5]);
    bd[4] = p3 ? bd[3] : (p4 ? d : bd[4]); bj[4] = p3 ? bj[3] : (p4 ? j : bj[4]);
    bd[3] = p2 ? bd[2] : (p3 ? d : bd[3]); bj[3] = p2 ? bj[2] : (p3 ? j : bj[3]);
    bd[2] = p1 ? bd[1] : (p2 ? d : bd[2]); bj[2] = p1 ? bj[1] : (p2 ? j : bj[2]);
    bd[1] = p0 ? bd[0] : (p1 ? d : bd[1]); bj[1] = p0 ? bj[0] : (p1 ? j : bj[1]);
    bd[0] = p0 ? d : bd[0];              bj[0] = p0 ? j : bj[0];
}

// ---------------- KNN phase 1: 256 blocks = 128 point-groups x 2 candidate-halves ----
// Block: 64 points x 4 parts x 1024 candidates; smem 82KB -> 2 blocks/SM (16 warps).
__global__ void k_knn_part() {
    extern __shared__ char sm[];
    float4* sp = (float4*)sm;                               // 4096 float4 = 64KB
    float*  md = (float*)(sm + 4096 * 16);                  // 64*33
    int*    mi = (int*)(sm + 4096 * 16 + 64 * 33 * 4);

    int tid = threadIdx.x;
    int g = blockIdx.x >> 1, h = blockIdx.x & 1;
    int cbase = h * 4096;
    for (int t = tid; t < 4096; t += 256) sp[t] = g_pts4[cbase + t];
    __syncthreads();

    int part = tid >> 6;          // warp-uniform
    int lp   = tid & 63;
    int pt   = g * 64 + lp;
    float4 me = g_pts4[pt];

    float bd[8]; int bj[8];
#pragma unroll
    for (int s = 0; s < 8; s++) { bd[s] = 3.4e38f; bj[s] = 0x7fffffff; }

    int j0 = part * 1024;
#pragma unroll 2
    for (int jj = 0; jj < 1024; jj += 2) {
        float4 o0 = sp[j0 + jj];
        float4 o1 = sp[j0 + jj + 1];
        float dot0 = fmaf(me.x, o0.x, fmaf(me.y, o0.y, me.z * o0.z));
        float dot1 = fmaf(me.x, o1.x, fmaf(me.y, o1.y, me.z * o1.z));
        float d0 = fmaf(-2.0f, dot0, me.w + o0.w);
        float d1 = fmaf(-2.0f, dot1, me.w + o1.w);
        if (fminf(d0, d1) < bd[7]) {
            if (d0 < bd[7]) ins8(bd, bj, d0, cbase + j0 + jj);
            if (d1 < bd[7]) ins8(bd, bj, d1, cbase + j0 + jj + 1);
        }
    }
#pragma unroll
    for (int s = 0; s < 8; s++) {
        md[lp * 33 + part * 8 + s] = bd[s];
        mi[lp * 33 + part * 8 + s] = bj[s];
    }
    __syncthreads();

    if (tid < 64) {               // merge 4 parts -> 8 (lex-min extraction)
        float* rd = md + tid * 33;
        int*   ri = mi + tid * 33;
        int po = (h * NPTS + g * 64 + tid) * KNN;
        for (int s = 0; s < 8; s++) {
            float bdd = 3.4e38f; int bjj = 0x7fffffff; int bp = 0;
            for (int t = 0; t < 32; t++) {
                float dd = rd[t]; int jx = ri[t];
                if (dd < bdd || (dd == bdd && jx < bjj)) { bdd = dd; bjj = jx; bp = t; }
            }
            rd[bp] = 3.4e38f;
            g_pd[po + s] = bdd;
            g_pj[po + s] = bjj;
        }
    }
}

// ---------------- KNN phase 2: merge the 2 halves' top-8 -> global top-8 ----------
__global__ void k_kmerge() {
    int pt = blockIdx.x * 256 + threadIdx.x;
    if (pt >= NPTS) return;
    float d[16]; int jx[16];
#pragma unroll
    for (int s = 0; s < 8; s++) {
        d[s]      = g_pd[pt * KNN + s];          jx[s]      = g_pj[pt * KNN + s];
        d[s + 8]  = g_pd[(NPTS + pt) * KNN + s]; jx[s + 8]  = g_pj[(NPTS + pt) * KNN + s];
    }
#pragma unroll
    for (int s = 0; s < 8; s++) {
        float bdd = 3.4e38f; int bjj = 0x7fffffff; int bp = 0;
#pragma unroll
        for (int t = 0; t < 16; t++) {
            if (d[t] < bdd || (d[t] == bdd && jx[t] < bjj)) { bdd = d[t]; bjj = jx[t]; bp = t; }
        }
        d[bp] = 3.4e38f;
        g_idx[pt * KNN + s] = bjj;
    }
}

// ---------------- P1 ----------------
__global__ void k_lin1(const float* __restrict__ W1, const float* __restrict__ pc) {
    int g = blockIdx.x * blockDim.x + threadIdx.x;
    if (g >= NPTS * 32) return;
    int i = g >> 5, q = g & 31;
    float x0 = pc[3*i], x1 = pc[3*i+1], x2 = pc[3*i+2];
    bool isQ = (q < 16);
    int c = (isQ ? q : q - 16) * 4;
    float v[4];
#pragma unroll
    for (int u = 0; u < 4; u++) {
        float wa0 = W1[0*64 + c+u], wa1 = W1[1*64 + c+u], wa2 = W1[2*64 + c+u];
        float wb0 = W1[3*64 + c+u], wb1 = W1[4*64 + c+u], wb2 = W1[5*64 + c+u];
        if (isQ) v[u] = x0*(wa0-wb0) + x1*(wa1-wb1) + x2*(wa2-wb2);
        else     v[u] = x0*wb0 + x1*wb1 + x2*wb2;
    }
    *(float4*)&g_qp1[i * 128 + q * 4] = make_float4(v[0], v[1], v[2], v[3]);
}

// ---------------- Wcat ----------------
__global__ void k_wcat(const float* __restrict__ W3) {
    int g = blockIdx.x * blockDim.x + threadIdx.x;
    if (g >= 128 * 256) return;
    int m = g >> 8, n = g & 255;
    float v;
    if (n < 128) v = W3[m * 128 + n] - W3[(m + 128) * 128 + n];
    else         v = W3[(m + 128) * 128 + (n - 128)];
    g_wcat[m * 256 + n] = v;
}

// ---------------- fused GEMM (R11 shape, proven) ----------------
template<int KDIM, int KC, int NOUT, bool EDGE, bool RELU_OUT>
__global__ void __launch_bounds__(256) k_gemm(
    const float* __restrict__ qA, const float* __restrict__ pB, int qstride,
    const float* __restrict__ bK, const float* __restrict__ Wg,
    const float* __restrict__ bN, float* __restrict__ out)
{
    extern __shared__ float smf[];
    float* As = smf;
    float* Ws = smf + KDIM * 64;
    int tid = threadIdx.x;
    int blk = blockIdx.x;
    int nt0 = blockIdx.y * 128;

    {
        const int TASKS = 64 * (KDIM / 4);
        int base64 = blk * 64;
        for (int t = tid; t < TASKS; t += 256) {
            int rr = t & 63, c4 = t >> 6;
            float4 v;
            if (EDGE) {
                int i = (base64 + rr) >> 3;
                int j = g_idx[base64 + rr];
                float4 q = *(const float4*)&qA[i * qstride + c4 * 4];
                float4 p = *(const float4*)&pB[(long)j * qstride + c4 * 4];
                float4 b = *(const float4*)&bK[c4 * 4];
                v.x = fmaxf(q.x + p.x + b.x, 0.0f);
                v.y = fmaxf(q.y + p.y + b.y, 0.0f);
                v.z = fmaxf(q.z + p.z + b.z, 0.0f);
                v.w = fmaxf(q.w + p.w + b.w, 0.0f);
            } else {
                v = *(const float4*)&qA[(long)(base64 + rr) * qstride + c4 * 4];
            }
            As[(c4*4 + 0) * 64 + rr] = v.x;
            As[(c4*4 + 1) * 64 + rr] = v.y;
            As[(c4*4 + 2) * 64 + rr] = v.z;
            As[(c4*4 + 3) * 64 + rr] = v.w;
        }
    }

    int tm = tid >> 5, tn = tid & 31;
    u64t acc2[4][4];
#pragma unroll
    for (int p = 0; p < 4; p++)
#pragma unroll
        for (int n = 0; n < 4; n++) acc2[p][n] = 0ull;

    const float4* Wg4 = (const float4*)Wg;
    for (int kc = 0; kc < KDIM / KC; kc++) {
        __syncthreads();
        {
            float4* Ws4 = (float4*)Ws;
#pragma unroll 4
            for (int t = tid; t < KC * 32; t += 256)
                Ws4[t] = Wg4[((kc * KC + (t >> 5)) * NOUT + nt0) / 4 + (t & 31)];
        }
        __syncthreads();

        const float* Ak = As + kc * KC * 64;
#pragma unroll 4
        for (int c = 0; c < KC; c++) {
            ulonglong2 av0 = *(const ulonglong2*)&Ak[c * 64 + tm * 8];
            ulonglong2 av1 = *(const ulonglong2*)&Ak[c * 64 + tm * 8 + 4];
            u64t ap[4] = {av0.x, av0.y, av1.x, av1.y};
            float4 w = *(const float4*)&Ws[c * 128 + tn * 4];
            u64t wd[4] = {pk2(w.x), pk2(w.y), pk2(w.z), pk2(w.w)};
#pragma unroll
            for (int p = 0; p < 4; p++)
#pragma unroll
                for (int n = 0; n < 4; n++)
                    acc2[p][n] = f2fma(ap[p], wd[n], acc2[p][n]);
        }
    }

    if (EDGE) {
        int pt = blk * 8 + tm;
        float res[4];
#pragma unroll
        for (int n = 0; n < 4; n++) {
            float2 v0 = up2(acc2[0][n]);
            float2 v1 = up2(acc2[1][n]);
            float2 v2 = up2(acc2[2][n]);
            float2 v3 = up2(acc2[3][n]);
            float m = fmaxf(fmaxf(fmaxf(v0.x, v0.y), fmaxf(v1.x, v1.y)),
                            fmaxf(fmaxf(v2.x, v2.y), fmaxf(v3.x, v3.y)));
            m += bN[nt0 + tn * 4 + n];
            if (RELU_OUT) m = fmaxf(m, 0.0f);
            res[n] = m;
        }
        *(float4*)&out[(long)pt * NOUT + nt0 + tn * 4] =
            make_float4(res[0], res[1], res[2], res[3]);
    } else {
        int base = blk * 64;
#pragma unroll
        for (int p = 0; p < 4; p++) {
            float2 c0 = up2(acc2[p][0]);
            float2 c1 = up2(acc2[p][1]);
            float2 c2 = up2(acc2[p][2]);
            float2 c3 = up2(acc2[p][3]);
            int row0 = base + tm * 8 + 2 * p;
            *(float4*)&out[(long)row0 * NOUT + nt0 + tn * 4] =
                make_float4(c0.x, c1.x, c2.x, c3.x);
            *(float4*)&out[(long)(row0 + 1) * NOUT + nt0 + tn * 4] =
                make_float4(c0.y, c1.y, c2.y, c3.y);
        }
    }
}

// ---------------- launch ----------------
extern "C" void kernel_launch(void* const* d_in, const int* in_sizes, int n_in,
                              void* d_out, int out_size) {
    const float* pc = (const float*)d_in[0];
    const float* W1 = (const float*)d_in[1];
    const float* b1 = (const float*)d_in[2];
    const float* W2 = (const float*)d_in[3];
    const float* b2 = (const float*)d_in[4];
    const float* W3 = (const float*)d_in[5];
    const float* b3 = (const float*)d_in[6];
    const float* W4 = (const float*)d_in[7];
    const float* b4 = (const float*)d_in[8];
    float* out = (float*)d_out;

    float *qp1 = nullptr, *x1 = nullptr, *qp2 = nullptr, *wcat = nullptr;
    cudaGetSymbolAddress((void**)&qp1,  g_qp1);
    cudaGetSymbolAddress((void**)&x1,   g_x1);
    cudaGetSymbolAddress((void**)&qp2,  g_qp2);
    cudaGetSymbolAddress((void**)&wcat, g_wcat);

    const int SM_KNN = 4096 * 16 + 2 * 64 * 33 * 4;                 // ~82KB -> 2/SM
    const int SM_EC1 = (64 * 64 + 64 * 128) * 4;                    // 48KB -> 4/SM
    const int SM_BIG = (128 * 64 + 64 * 128) * 4;                   // 64KB -> 3/SM

    cudaFuncSetAttribute(k_knn_part, cudaFuncAttributeMaxDynamicSharedMemorySize, SM_KNN);
    cudaFuncSetAttribute((const void*)k_gemm<64,64,128,true,true>,
                         cudaFuncAttributeMaxDynamicSharedMemorySize, SM_EC1);
    cudaFuncSetAttribute((const void*)k_gemm<128,64,256,false,false>,
                         cudaFuncAttributeMaxDynamicSharedMemorySize, SM_BIG);
    cudaFuncSetAttribute((const void*)k_gemm<128,64,256,true,false>,
                         cudaFuncAttributeMaxDynamicSharedMemorySize, SM_BIG);

    // 1. per-point linear factors (indep)
    k_lin1<<<(NPTS * 32 + 255) / 256, 256>>>(W1, pc);
    // 2. Wcat (indep)
    k_wcat<<<(128 * 256 + 255) / 256, 256>>>(W3);
    // 3. pack points
    k_prep<<<(NPTS + 255) / 256, 256>>>(pc);
    // 4. knn phase 1  <-- profiled slot
    k_knn_part<<<256, 256, SM_KNN>>>();
    // 5. knn phase 2 (merge halves)
    k_kmerge<<<NPTS / 256, 256>>>();
    // 6. EdgeConv1 (R11 shape)
    k_gemm<64,64,128,true,true><<<dim3(NPTS * KNN / 64, 1), 256, SM_EC1>>>(
        qp1, qp1 + 64, 128, b1, W2, b2, x1);
    // 7. P2
    k_gemm<128,64,256,false,false><<<dim3(NPTS / 64, 2), 256, SM_BIG>>>(
        x1, nullptr, 128, nullptr, wcat, nullptr, qp2);
    // 8. EdgeConv2
    k_gemm<128,64,256,true,false><<<dim3(NPTS * KNN / 64, 2), 256, SM_BIG>>>(
        qp2, qp2 + 128, 256, b3, W4, b4, out);
}